// round 1
// baseline (speedup 1.0000x reference)
#include <cuda_runtime.h>

// Problem constants
#define B_  4
#define L_  2048
#define D_  1024
#define H_  16
#define HD_ 64
#define NT_ (B_ * L_)          // 8192 tokens
#define BH_ (B_ * H_)          // 64 head-streams

// Scratch: qkv in [3][B*H][L][HD] layout, ctx in [B,L,D] layout.
__device__ float g_qkv[(size_t)3 * BH_ * L_ * HD_];   // ~100.7 MB
__device__ float g_ctx[(size_t)NT_ * D_];             // ~33.5 MB

// ---------------------------------------------------------------------------
// Generic tiled GEMM: C[M,N] = A[M,K] * B[N,K]^T   (both row-major)
// BM=BN=64, BK=16, 256 threads, 4x4 per-thread tile.
// mode 0: plain row-major store to C.
// mode 1: scatter QKV columns into g_qkv [3][B*H][L][HD].
// ---------------------------------------------------------------------------
__global__ __launch_bounds__(256) void gemm_bt_kernel(
    const float* __restrict__ A, const float* __restrict__ Bm,
    float* __restrict__ C, int M, int N, int K, int mode)
{
    __shared__ float As[16][68];   // [k][m], padded for float4 align + banks
    __shared__ float Bs[16][68];   // [k][n]

    const int t  = threadIdx.x;
    const int tx = t & 15;
    const int ty = t >> 4;
    const int m0 = blockIdx.y * 64;
    const int n0 = blockIdx.x * 64;
    const int lr = t >> 2;          // 0..63 : row within tile for loading
    const int lc = (t & 3) * 4;     // 0,4,8,12 : k-col group for loading

    float acc[4][4] = {};

    for (int k0 = 0; k0 < K; k0 += 16) {
        float4 av = *(const float4*)(A  + (size_t)(m0 + lr) * K + k0 + lc);
        float4 bv = *(const float4*)(Bm + (size_t)(n0 + lr) * K + k0 + lc);
        As[lc + 0][lr] = av.x; As[lc + 1][lr] = av.y;
        As[lc + 2][lr] = av.z; As[lc + 3][lr] = av.w;
        Bs[lc + 0][lr] = bv.x; Bs[lc + 1][lr] = bv.y;
        Bs[lc + 2][lr] = bv.z; Bs[lc + 3][lr] = bv.w;
        __syncthreads();

        #pragma unroll
        for (int k = 0; k < 16; k++) {
            float4 a = *(const float4*)&As[k][ty * 4];
            float4 b = *(const float4*)&Bs[k][tx * 4];
            float ar[4] = {a.x, a.y, a.z, a.w};
            float br[4] = {b.x, b.y, b.z, b.w};
            #pragma unroll
            for (int i = 0; i < 4; i++)
                #pragma unroll
                for (int j = 0; j < 4; j++)
                    acc[i][j] += ar[i] * br[j];
        }
        __syncthreads();
    }

    if (mode == 0) {
        #pragma unroll
        for (int i = 0; i < 4; i++)
            #pragma unroll
            for (int j = 0; j < 4; j++)
                C[(size_t)(m0 + ty * 4 + i) * N + n0 + tx * 4 + j] = acc[i][j];
    } else {
        #pragma unroll
        for (int i = 0; i < 4; i++) {
            #pragma unroll
            for (int j = 0; j < 4; j++) {
                int m = m0 + ty * 4 + i;
                int n = n0 + tx * 4 + j;
                int b     = m >> 11;          // token -> batch
                int l     = m & 2047;
                int which = n >> 10;          // 0=Q 1=K 2=V
                int rem   = n & 1023;
                int h     = rem >> 6;
                int d     = rem & 63;
                size_t idx = (((size_t)(which * BH_ + b * H_ + h)) * L_ + l) * HD_ + d;
                C[idx] = acc[i][j];
            }
        }
    }
}

// ---------------------------------------------------------------------------
// Flash attention, fp32, causal. One CTA per (query-tile of 64, head-stream).
// 256 threads (16x16), 4x4 per-thread tiles for both S=QK^T and O+=PV.
// Dynamic smem: Qts/Kts (d-major, [64][68]), Vs (k-major), Ss.
// ---------------------------------------------------------------------------
__global__ __launch_bounds__(256) void attn_kernel(
    const float* __restrict__ qkv, float* __restrict__ ctx)
{
    const int qt = blockIdx.x;    // query tile 0..31
    const int bh = blockIdx.y;    // 0..63

    extern __shared__ float sm[];
    float* Qts = sm;                  // [d][q] pad 68
    float* Kts = sm + 64 * 68;        // [d][k] pad 68
    float* Vs  = sm + 2 * 64 * 68;    // [k][d] pad 68
    float* Ss  = sm + 3 * 64 * 68;    // [q][k] pad 68
    __shared__ float m_s[64], l_s[64], corr_s[64], red[256];

    const int t  = threadIdx.x;
    const int tx = t & 15;
    const int ty = t >> 4;
    const int lrow = t >> 4;          // 0..15 (row group for tile loads)
    const int lcol = (t & 15) * 4;    // 0..60

    const float* Qg = qkv + ((size_t)bh          * L_ + (size_t)qt * 64) * HD_;
    const float* Kg = qkv + ((size_t)(BH_ + bh)  * L_) * HD_;
    const float* Vg = qkv + ((size_t)(2*BH_ + bh)* L_) * HD_;

    // Load Q tile, transposed to d-major
    #pragma unroll
    for (int i = 0; i < 4; i++) {
        int r = i * 16 + lrow;
        float4 v = *(const float4*)(Qg + (size_t)r * HD_ + lcol);
        Qts[(lcol + 0) * 68 + r] = v.x;
        Qts[(lcol + 1) * 68 + r] = v.y;
        Qts[(lcol + 2) * 68 + r] = v.z;
        Qts[(lcol + 3) * 68 + r] = v.w;
    }
    if (t < 64) { m_s[t] = -3.0e38f; l_s[t] = 0.0f; }

    float acc[4][4] = {};
    const int r   = t >> 2;   // softmax row 0..63
    const int seg = t & 3;    // softmax segment 0..3

    for (int kt = 0; kt <= qt; kt++) {
        __syncthreads();   // prior tile done with Vs/Ss; Q/init visible (1st iter)

        // Load K tile (transposed) and V tile (direct)
        #pragma unroll
        for (int i = 0; i < 4; i++) {
            int rr = i * 16 + lrow;
            float4 kv = *(const float4*)(Kg + ((size_t)(kt * 64 + rr)) * HD_ + lcol);
            Kts[(lcol + 0) * 68 + rr] = kv.x;
            Kts[(lcol + 1) * 68 + rr] = kv.y;
            Kts[(lcol + 2) * 68 + rr] = kv.z;
            Kts[(lcol + 3) * 68 + rr] = kv.w;
            float4 vv = *(const float4*)(Vg + ((size_t)(kt * 64 + rr)) * HD_ + lcol);
            *(float4*)&Vs[rr * 68 + lcol] = vv;
        }
        __syncthreads();

        // S = Q K^T  (4x4 per thread)
        float s[4][4] = {};
        #pragma unroll
        for (int d = 0; d < 64; d++) {
            float4 a = *(const float4*)&Qts[d * 68 + ty * 4];
            float4 b = *(const float4*)&Kts[d * 68 + tx * 4];
            float ar[4] = {a.x, a.y, a.z, a.w};
            float br[4] = {b.x, b.y, b.z, b.w};
            #pragma unroll
            for (int i = 0; i < 4; i++)
                #pragma unroll
                for (int j = 0; j < 4; j++)
                    s[i][j] += ar[i] * br[j];
        }

        // scale + causal mask + store S
        #pragma unroll
        for (int i = 0; i < 4; i++) {
            int qg = qt * 64 + ty * 4 + i;
            #pragma unroll
            for (int j = 0; j < 4; j++) {
                int kg = kt * 64 + tx * 4 + j;
                Ss[(ty * 4 + i) * 68 + tx * 4 + j] =
                    (kg <= qg) ? s[i][j] * 0.125f : -1.0e30f;
            }
        }
        __syncthreads();

        // softmax pass 1: per-row partial max (4 threads/row, 16 cols each)
        float pm = -3.0e38f;
        #pragma unroll
        for (int u = 0; u < 16; u++)
            pm = fmaxf(pm, Ss[r * 68 + seg * 16 + u]);
        red[r * 4 + seg] = pm;
        __syncthreads();

        if (seg == 0) {
            float rm = fmaxf(fmaxf(red[r * 4], red[r * 4 + 1]),
                             fmaxf(red[r * 4 + 2], red[r * 4 + 3]));
            float mo = m_s[r];
            float mn = fmaxf(mo, rm);
            corr_s[r] = __expf(mo - mn);
            m_s[r] = mn;
        }
        __syncthreads();

        // pass 2: exponentiate in place, accumulate partial row sums
        float mn = m_s[r];
        float ps = 0.0f;
        #pragma unroll
        for (int u = 0; u < 16; u++) {
            float p = __expf(Ss[r * 68 + seg * 16 + u] - mn);
            Ss[r * 68 + seg * 16 + u] = p;
            ps += p;
        }
        red[r * 4 + seg] = ps;
        __syncthreads();

        if (seg == 0)
            l_s[r] = l_s[r] * corr_s[r] +
                     red[r * 4] + red[r * 4 + 1] + red[r * 4 + 2] + red[r * 4 + 3];

        // rescale accumulator
        #pragma unroll
        for (int i = 0; i < 4; i++) {
            float c = corr_s[ty * 4 + i];
            #pragma unroll
            for (int j = 0; j < 4; j++) acc[i][j] *= c;
        }

        // O += P V
        #pragma unroll
        for (int k = 0; k < 64; k++) {
            float4 b = *(const float4*)&Vs[k * 68 + tx * 4];
            float br[4] = {b.x, b.y, b.z, b.w};
            #pragma unroll
            for (int i = 0; i < 4; i++) {
                float a = Ss[(ty * 4 + i) * 68 + k];
                #pragma unroll
                for (int j = 0; j < 4; j++)
                    acc[i][j] += a * br[j];
            }
        }
    }
    __syncthreads();   // l_s final values visible

    // normalize and write ctx in [B, L, H*HD] = [B, L, D] layout
    const int b = bh >> 4;
    const int h = bh & 15;
    #pragma unroll
    for (int i = 0; i < 4; i++) {
        int l = qt * 64 + ty * 4 + i;
        float inv = 1.0f / l_s[ty * 4 + i];
        #pragma unroll
        for (int j = 0; j < 4; j++) {
            size_t idx = (((size_t)b * L_ + l) * H_ + h) * HD_ + tx * 4 + j;
            ctx[idx] = acc[i][j] * inv;
        }
    }
}

// ---------------------------------------------------------------------------
extern "C" void kernel_launch(void* const* d_in, const int* in_sizes, int n_in,
                              void* d_out, int out_size)
{
    const float* x     = (const float*)d_in[0];   // [B,L,D]
    const float* W_qkv = (const float*)d_in[1];   // [3D, D]
    const float* W_out = (const float*)d_in[2];   // [D, D]
    float* out = (float*)d_out;                   // [B,L,D]

    float* qkv_ptr = nullptr;
    float* ctx_ptr = nullptr;
    cudaGetSymbolAddress((void**)&qkv_ptr, g_qkv);
    cudaGetSymbolAddress((void**)&ctx_ptr, g_ctx);

    const int attn_smem = 4 * 64 * 68 * (int)sizeof(float);   // 69632 B
    cudaFuncSetAttribute(attn_kernel,
                         cudaFuncAttributeMaxDynamicSharedMemorySize, attn_smem);

    // 1) QKV projection with scatter epilogue
    gemm_bt_kernel<<<dim3(3 * D_ / 64, NT_ / 64), 256>>>(
        x, W_qkv, qkv_ptr, NT_, 3 * D_, D_, 1);

    // 2) causal flash attention
    attn_kernel<<<dim3(L_ / 64, BH_), 256, attn_smem>>>(qkv_ptr, ctx_ptr);

    // 3) output projection
    gemm_bt_kernel<<<dim3(D_ / 64, NT_ / 64), 256>>>(
        ctx_ptr, W_out, out, NT_, D_, D_, 0);
}

// round 4
// speedup vs baseline: 1.3074x; 1.3074x over previous
#include <cuda_runtime.h>
#include <cstdint>

// Problem constants
#define B_  4
#define L_  2048
#define D_  1024
#define H_  16
#define HD_ 64
#define NT_ (B_ * L_)          // 8192 tokens
#define BH_ (B_ * H_)          // 64 head-streams

// Scratch: qkv in [3][B*H][L][HD] layout, ctx in [B,L,D] layout.
__device__ float g_qkv[(size_t)3 * BH_ * L_ * HD_];   // ~100.7 MB
__device__ float g_ctx[(size_t)NT_ * D_];             // ~33.5 MB

__device__ __forceinline__ uint32_t smem_u32(const void* p) {
    uint32_t a;
    asm("{ .reg .u64 t; cvta.to.shared.u64 t, %1; cvt.u32.u64 %0, t; }"
        : "=r"(a) : "l"(p));
    return a;
}

__device__ __forceinline__ void cp_async16(uint32_t saddr, const void* gaddr) {
    asm volatile("cp.async.cg.shared.global [%0], [%1], 16;"
                 :: "r"(saddr), "l"(gaddr) : "memory");
}
__device__ __forceinline__ void cp_commit() {
    asm volatile("cp.async.commit_group;" ::: "memory");
}
__device__ __forceinline__ void cp_wait1() {
    asm volatile("cp.async.wait_group 1;" ::: "memory");
}
__device__ __forceinline__ void cp_wait0() {
    asm volatile("cp.async.wait_group 0;" ::: "memory");
}

// mma.sync m16n8k8 tf32: D = A*B + D  (A row-major 16x8, B col-major 8x8)
__device__ __forceinline__ void mma_tf32(float& c0, float& c1, float& c2, float& c3,
                                         uint32_t a0, uint32_t a1, uint32_t a2, uint32_t a3,
                                         uint32_t b0, uint32_t b1) {
    asm volatile(
        "mma.sync.aligned.m16n8k8.row.col.f32.tf32.tf32.f32 "
        "{%0,%1,%2,%3}, {%4,%5,%6,%7}, {%8,%9}, {%0,%1,%2,%3};"
        : "+f"(c0), "+f"(c1), "+f"(c2), "+f"(c3)
        : "r"(a0), "r"(a1), "r"(a2), "r"(a3), "r"(b0), "r"(b1));
}

// Split fp32 into tf32 hi (round-to-nearest) + residual lo (exact in fp32;
// hardware truncation of lo's low bits costs only ~2^-22 relative).
__device__ __forceinline__ void split_tf32(uint32_t x, uint32_t& hi, uint32_t& lo) {
    float f = __uint_as_float(x);
    uint32_t h;
    asm("cvt.rna.tf32.f32 %0, %1;" : "=r"(h) : "f"(f));
    hi = h;
    lo = __float_as_uint(f - __uint_as_float(h));
}

// ---------------------------------------------------------------------------
// 3xTF32 split-precision GEMM via mma.sync: C[M,N] = A[M,K] * B[N,K]^T.
// CTA 128x128, BK=32, 8 warps (2M x 4N), warp tile 64x32, double-buffered
// cp.async staging. Smem rows padded to 36 floats (conflict-free fragments).
// Per product: hi*hi + hi*lo + lo*hi  => fp32-class accuracy on tensor cores.
// mode 0: plain store; mode 1: QKV scatter into [3][B*H][L][HD].
// ---------------------------------------------------------------------------
#define PAD_ 36
#define TILE_FLOATS (128 * PAD_)                 // 4608 floats = 18432 B
#define STAGE_FLOATS (2 * TILE_FLOATS)           // A + B
#define GK_SMEM_BYTES (2 * STAGE_FLOATS * 4)     // 73728 B

__global__ __launch_bounds__(256) void gemm_tc_kernel(
    const float* __restrict__ A, const float* __restrict__ Bm,
    float* __restrict__ C, int M, int N, int K, int mode)
{
    extern __shared__ float smem[];   // [stage][A(128*36) | B(128*36)]

    const int t    = threadIdx.x;
    const int wid  = t >> 5;
    const int lane = t & 31;
    const int g    = lane >> 2;       // group id 0..7
    const int c4   = lane & 3;        // 0..3
    const int m0   = blockIdx.y * 128;
    const int n0   = blockIdx.x * 128;
    const int wm   = (wid & 1) * 64;  // warp M offset
    const int wn   = (wid >> 1) * 32; // warp N offset

    float acc[4][4][4] = {};

    const int nchunks = K >> 5;

    // ---- prefetch chunk 0 ----
    {
        const uint32_t sA = smem_u32(smem);
        const uint32_t sB = sA + TILE_FLOATS * 4;
        #pragma unroll
        for (int u = 0; u < 4; u++) {
            int idx = t + u * 256;
            int row = idx >> 3;
            int grp = idx & 7;
            cp_async16(sA + (row * PAD_ + grp * 4) * 4,
                       A  + (size_t)(m0 + row) * K + grp * 4);
            cp_async16(sB + (row * PAD_ + grp * 4) * 4,
                       Bm + (size_t)(n0 + row) * K + grp * 4);
        }
        cp_commit();
    }

    for (int c = 0; c < nchunks; c++) {
        if (c + 1 < nchunks) {
            const int s = (c + 1) & 1;
            const int k0 = (c + 1) * 32;
            const uint32_t sA = smem_u32(smem + s * STAGE_FLOATS);
            const uint32_t sB = sA + TILE_FLOATS * 4;
            #pragma unroll
            for (int u = 0; u < 4; u++) {
                int idx = t + u * 256;
                int row = idx >> 3;
                int grp = idx & 7;
                cp_async16(sA + (row * PAD_ + grp * 4) * 4,
                           A  + (size_t)(m0 + row) * K + k0 + grp * 4);
                cp_async16(sB + (row * PAD_ + grp * 4) * 4,
                           Bm + (size_t)(n0 + row) * K + k0 + grp * 4);
            }
            cp_commit();
            cp_wait1();
        } else {
            cp_wait0();
        }
        __syncthreads();

        const float* As = smem + (c & 1) * STAGE_FLOATS;
        const float* Bs = As + TILE_FLOATS;
        const uint32_t* Au = (const uint32_t*)As;
        const uint32_t* Bu = (const uint32_t*)Bs;

        #pragma unroll
        for (int kk = 0; kk < 32; kk += 8) {
            uint32_t ah[4][4], al[4][4], bh[4][2], bl[4][2];
            #pragma unroll
            for (int mi = 0; mi < 4; mi++) {
                const uint32_t* base = Au + (wm + mi * 16 + g) * PAD_ + kk + c4;
                uint32_t r0 = base[0];
                uint32_t r1 = base[8 * PAD_];
                uint32_t r2 = base[4];
                uint32_t r3 = base[8 * PAD_ + 4];
                split_tf32(r0, ah[mi][0], al[mi][0]);
                split_tf32(r1, ah[mi][1], al[mi][1]);
                split_tf32(r2, ah[mi][2], al[mi][2]);
                split_tf32(r3, ah[mi][3], al[mi][3]);
            }
            #pragma unroll
            for (int ni = 0; ni < 4; ni++) {
                const uint32_t* base = Bu + (wn + ni * 8 + g) * PAD_ + kk + c4;
                uint32_t r0 = base[0];
                uint32_t r1 = base[4];
                split_tf32(r0, bh[ni][0], bl[ni][0]);
                split_tf32(r1, bh[ni][1], bl[ni][1]);
            }
            #pragma unroll
            for (int mi = 0; mi < 4; mi++)
                #pragma unroll
                for (int ni = 0; ni < 4; ni++) {
                    // lo terms first, hi*hi last (slightly better rounding)
                    mma_tf32(acc[mi][ni][0], acc[mi][ni][1],
                             acc[mi][ni][2], acc[mi][ni][3],
                             ah[mi][0], ah[mi][1], ah[mi][2], ah[mi][3],
                             bl[ni][0], bl[ni][1]);
                    mma_tf32(acc[mi][ni][0], acc[mi][ni][1],
                             acc[mi][ni][2], acc[mi][ni][3],
                             al[mi][0], al[mi][1], al[mi][2], al[mi][3],
                             bh[ni][0], bh[ni][1]);
                    mma_tf32(acc[mi][ni][0], acc[mi][ni][1],
                             acc[mi][ni][2], acc[mi][ni][3],
                             ah[mi][0], ah[mi][1], ah[mi][2], ah[mi][3],
                             bh[ni][0], bh[ni][1]);
                }
        }
        __syncthreads();
    }

    // ---- epilogue: c-frag rows g/g+8, col pairs (2*c4, 2*c4+1) ----
    #pragma unroll
    for (int mi = 0; mi < 4; mi++) {
        #pragma unroll
        for (int half = 0; half < 2; half++) {
            const int m = m0 + wm + mi * 16 + g + half * 8;
            if (mode == 0) {
                #pragma unroll
                for (int ni = 0; ni < 4; ni++) {
                    int n = n0 + wn + ni * 8 + c4 * 2;
                    float2 v = half == 0
                        ? make_float2(acc[mi][ni][0], acc[mi][ni][1])
                        : make_float2(acc[mi][ni][2], acc[mi][ni][3]);
                    *(float2*)(C + (size_t)m * N + n) = v;
                }
            } else {
                const int b = m >> 11;
                const int l = m & 2047;
                #pragma unroll
                for (int ni = 0; ni < 4; ni++) {
                    int n     = n0 + wn + ni * 8 + c4 * 2;
                    int which = n >> 10;
                    int rem   = n & 1023;
                    int h     = rem >> 6;
                    int d     = rem & 63;
                    size_t idx = (((size_t)(which * BH_ + b * H_ + h)) * L_ + l) * HD_ + d;
                    float2 v = half == 0
                        ? make_float2(acc[mi][ni][0], acc[mi][ni][1])
                        : make_float2(acc[mi][ni][2], acc[mi][ni][3]);
                    *(float2*)(C + idx) = v;
                }
            }
        }
    }
}

// ---------------------------------------------------------------------------
// Flash attention, fp32, causal (unchanged — fp32 SIMT, ~1ms).
// ---------------------------------------------------------------------------
__global__ __launch_bounds__(256) void attn_kernel(
    const float* __restrict__ qkv, float* __restrict__ ctx)
{
    const int qt = blockIdx.x;    // query tile 0..31
    const int bh = blockIdx.y;    // 0..63

    extern __shared__ float sm[];
    float* Qts = sm;                  // [d][q] pad 68
    float* Kts = sm + 64 * 68;        // [d][k] pad 68
    float* Vs  = sm + 2 * 64 * 68;    // [k][d] pad 68
    float* Ss  = sm + 3 * 64 * 68;    // [q][k] pad 68
    __shared__ float m_s[64], l_s[64], corr_s[64], red[256];

    const int t  = threadIdx.x;
    const int tx = t & 15;
    const int ty = t >> 4;
    const int lrow = t >> 4;
    const int lcol = (t & 15) * 4;

    const float* Qg = qkv + ((size_t)bh          * L_ + (size_t)qt * 64) * HD_;
    const float* Kg = qkv + ((size_t)(BH_ + bh)  * L_) * HD_;
    const float* Vg = qkv + ((size_t)(2*BH_ + bh)* L_) * HD_;

    #pragma unroll
    for (int i = 0; i < 4; i++) {
        int r = i * 16 + lrow;
        float4 v = *(const float4*)(Qg + (size_t)r * HD_ + lcol);
        Qts[(lcol + 0) * 68 + r] = v.x;
        Qts[(lcol + 1) * 68 + r] = v.y;
        Qts[(lcol + 2) * 68 + r] = v.z;
        Qts[(lcol + 3) * 68 + r] = v.w;
    }
    if (t < 64) { m_s[t] = -3.0e38f; l_s[t] = 0.0f; }

    float acc[4][4] = {};
    const int r   = t >> 2;
    const int seg = t & 3;

    for (int kt = 0; kt <= qt; kt++) {
        __syncthreads();

        #pragma unroll
        for (int i = 0; i < 4; i++) {
            int rr = i * 16 + lrow;
            float4 kv = *(const float4*)(Kg + ((size_t)(kt * 64 + rr)) * HD_ + lcol);
            Kts[(lcol + 0) * 68 + rr] = kv.x;
            Kts[(lcol + 1) * 68 + rr] = kv.y;
            Kts[(lcol + 2) * 68 + rr] = kv.z;
            Kts[(lcol + 3) * 68 + rr] = kv.w;
            float4 vv = *(const float4*)(Vg + ((size_t)(kt * 64 + rr)) * HD_ + lcol);
            *(float4*)&Vs[rr * 68 + lcol] = vv;
        }
        __syncthreads();

        float s[4][4] = {};
        #pragma unroll
        for (int d = 0; d < 64; d++) {
            float4 a = *(const float4*)&Qts[d * 68 + ty * 4];
            float4 b = *(const float4*)&Kts[d * 68 + tx * 4];
            float ar[4] = {a.x, a.y, a.z, a.w};
            float br[4] = {b.x, b.y, b.z, b.w};
            #pragma unroll
            for (int i = 0; i < 4; i++)
                #pragma unroll
                for (int j = 0; j < 4; j++)
                    s[i][j] += ar[i] * br[j];
        }

        #pragma unroll
        for (int i = 0; i < 4; i++) {
            int qg = qt * 64 + ty * 4 + i;
            #pragma unroll
            for (int j = 0; j < 4; j++) {
                int kg = kt * 64 + tx * 4 + j;
                Ss[(ty * 4 + i) * 68 + tx * 4 + j] =
                    (kg <= qg) ? s[i][j] * 0.125f : -1.0e30f;
            }
        }
        __syncthreads();

        float pm = -3.0e38f;
        #pragma unroll
        for (int u = 0; u < 16; u++)
            pm = fmaxf(pm, Ss[r * 68 + seg * 16 + u]);
        red[r * 4 + seg] = pm;
        __syncthreads();

        if (seg == 0) {
            float rm = fmaxf(fmaxf(red[r * 4], red[r * 4 + 1]),
                             fmaxf(red[r * 4 + 2], red[r * 4 + 3]));
            float mo = m_s[r];
            float mn = fmaxf(mo, rm);
            corr_s[r] = __expf(mo - mn);
            m_s[r] = mn;
        }
        __syncthreads();

        float mn = m_s[r];
        float ps = 0.0f;
        #pragma unroll
        for (int u = 0; u < 16; u++) {
            float p = __expf(Ss[r * 68 + seg * 16 + u] - mn);
            Ss[r * 68 + seg * 16 + u] = p;
            ps += p;
        }
        red[r * 4 + seg] = ps;
        __syncthreads();

        if (seg == 0)
            l_s[r] = l_s[r] * corr_s[r] +
                     red[r * 4] + red[r * 4 + 1] + red[r * 4 + 2] + red[r * 4 + 3];

        #pragma unroll
        for (int i = 0; i < 4; i++) {
            float c = corr_s[ty * 4 + i];
            #pragma unroll
            for (int j = 0; j < 4; j++) acc[i][j] *= c;
        }

        #pragma unroll
        for (int k = 0; k < 64; k++) {
            float4 b = *(const float4*)&Vs[k * 68 + tx * 4];
            float br[4] = {b.x, b.y, b.z, b.w};
            #pragma unroll
            for (int i = 0; i < 4; i++) {
                float a = Ss[(ty * 4 + i) * 68 + k];
                #pragma unroll
                for (int j = 0; j < 4; j++)
                    acc[i][j] += a * br[j];
            }
        }
    }
    __syncthreads();

    const int b = bh >> 4;
    const int h = bh & 15;
    #pragma unroll
    for (int i = 0; i < 4; i++) {
        int l = qt * 64 + ty * 4 + i;
        float inv = 1.0f / l_s[ty * 4 + i];
        #pragma unroll
        for (int j = 0; j < 4; j++) {
            size_t idx = (((size_t)b * L_ + l) * H_ + h) * HD_ + tx * 4 + j;
            ctx[idx] = acc[i][j] * inv;
        }
    }
}

// ---------------------------------------------------------------------------
extern "C" void kernel_launch(void* const* d_in, const int* in_sizes, int n_in,
                              void* d_out, int out_size)
{
    const float* x     = (const float*)d_in[0];   // [B,L,D]
    const float* W_qkv = (const float*)d_in[1];   // [3D, D]
    const float* W_out = (const float*)d_in[2];   // [D, D]
    float* out = (float*)d_out;                   // [B,L,D]

    float* qkv_ptr = nullptr;
    float* ctx_ptr = nullptr;
    cudaGetSymbolAddress((void**)&qkv_ptr, g_qkv);
    cudaGetSymbolAddress((void**)&ctx_ptr, g_ctx);

    cudaFuncSetAttribute(gemm_tc_kernel,
                         cudaFuncAttributeMaxDynamicSharedMemorySize, GK_SMEM_BYTES);
    const int attn_smem = 4 * 64 * 68 * (int)sizeof(float);   // 69632 B
    cudaFuncSetAttribute(attn_kernel,
                         cudaFuncAttributeMaxDynamicSharedMemorySize, attn_smem);

    // 1) QKV projection (3xTF32 mma.sync) with scatter epilogue
    gemm_tc_kernel<<<dim3(3 * D_ / 128, NT_ / 128), 256, GK_SMEM_BYTES>>>(
        x, W_qkv, qkv_ptr, NT_, 3 * D_, D_, 1);

    // 2) causal flash attention (fp32 SIMT)
    attn_kernel<<<dim3(L_ / 64, BH_), 256, attn_smem>>>(qkv_ptr, ctx_ptr);

    // 3) output projection (3xTF32 mma.sync)
    gemm_tc_kernel<<<dim3(D_ / 128, NT_ / 128), 256, GK_SMEM_BYTES>>>(
        ctx_ptr, W_out, out, NT_, D_, D_, 0);
}

// round 5
// speedup vs baseline: 1.5325x; 1.1722x over previous
#include <cuda_runtime.h>
#include <cstdint>

// Problem constants
#define B_  4
#define L_  2048
#define D_  1024
#define H_  16
#define HD_ 64
#define NT_ (B_ * L_)          // 8192 tokens
#define BH_ (B_ * H_)          // 64 head-streams

// Scratch: qkv in [3][B*H][L][HD] layout, ctx in [B,L,D] layout.
__device__ float g_qkv[(size_t)3 * BH_ * L_ * HD_];   // ~100.7 MB
__device__ float g_ctx[(size_t)NT_ * D_];             // ~33.5 MB

__device__ __forceinline__ uint32_t smem_u32(const void* p) {
    uint32_t a;
    asm("{ .reg .u64 t; cvta.to.shared.u64 t, %1; cvt.u32.u64 %0, t; }"
        : "=r"(a) : "l"(p));
    return a;
}

__device__ __forceinline__ void cp_async16(uint32_t saddr, const void* gaddr) {
    asm volatile("cp.async.cg.shared.global [%0], [%1], 16;"
                 :: "r"(saddr), "l"(gaddr) : "memory");
}
__device__ __forceinline__ void cp_commit() {
    asm volatile("cp.async.commit_group;" ::: "memory");
}
__device__ __forceinline__ void cp_wait1() {
    asm volatile("cp.async.wait_group 1;" ::: "memory");
}
__device__ __forceinline__ void cp_wait0() {
    asm volatile("cp.async.wait_group 0;" ::: "memory");
}

// mma.sync m16n8k8 tf32: D = A*B + D  (A row-major 16x8, B col-major 8x8)
__device__ __forceinline__ void mma_tf32(float& c0, float& c1, float& c2, float& c3,
                                         uint32_t a0, uint32_t a1, uint32_t a2, uint32_t a3,
                                         uint32_t b0, uint32_t b1) {
    asm volatile(
        "mma.sync.aligned.m16n8k8.row.col.f32.tf32.tf32.f32 "
        "{%0,%1,%2,%3}, {%4,%5,%6,%7}, {%8,%9}, {%0,%1,%2,%3};"
        : "+f"(c0), "+f"(c1), "+f"(c2), "+f"(c3)
        : "r"(a0), "r"(a1), "r"(a2), "r"(a3), "r"(b0), "r"(b1));
}

// Split fp32 into tf32 hi (round-to-nearest) + residual lo.
__device__ __forceinline__ void split_tf32(uint32_t x, uint32_t& hi, uint32_t& lo) {
    float f = __uint_as_float(x);
    uint32_t h;
    asm("cvt.rna.tf32.f32 %0, %1;" : "=r"(h) : "f"(f));
    hi = h;
    lo = __float_as_uint(f - __uint_as_float(h));
}

// ---------------------------------------------------------------------------
// 3xTF32 split-precision GEMM via mma.sync (unchanged from R4).
// ---------------------------------------------------------------------------
#define PAD_ 36
#define TILE_FLOATS (128 * PAD_)
#define STAGE_FLOATS (2 * TILE_FLOATS)
#define GK_SMEM_BYTES (2 * STAGE_FLOATS * 4)     // 73728 B

__global__ __launch_bounds__(256) void gemm_tc_kernel(
    const float* __restrict__ A, const float* __restrict__ Bm,
    float* __restrict__ C, int M, int N, int K, int mode)
{
    extern __shared__ float smem[];

    const int t    = threadIdx.x;
    const int wid  = t >> 5;
    const int lane = t & 31;
    const int g    = lane >> 2;
    const int c4   = lane & 3;
    const int m0   = blockIdx.y * 128;
    const int n0   = blockIdx.x * 128;
    const int wm   = (wid & 1) * 64;
    const int wn   = (wid >> 1) * 32;

    float acc[4][4][4] = {};
    const int nchunks = K >> 5;

    {
        const uint32_t sA = smem_u32(smem);
        const uint32_t sB = sA + TILE_FLOATS * 4;
        #pragma unroll
        for (int u = 0; u < 4; u++) {
            int idx = t + u * 256;
            int row = idx >> 3;
            int grp = idx & 7;
            cp_async16(sA + (row * PAD_ + grp * 4) * 4,
                       A  + (size_t)(m0 + row) * K + grp * 4);
            cp_async16(sB + (row * PAD_ + grp * 4) * 4,
                       Bm + (size_t)(n0 + row) * K + grp * 4);
        }
        cp_commit();
    }

    for (int c = 0; c < nchunks; c++) {
        if (c + 1 < nchunks) {
            const int s = (c + 1) & 1;
            const int k0 = (c + 1) * 32;
            const uint32_t sA = smem_u32(smem + s * STAGE_FLOATS);
            const uint32_t sB = sA + TILE_FLOATS * 4;
            #pragma unroll
            for (int u = 0; u < 4; u++) {
                int idx = t + u * 256;
                int row = idx >> 3;
                int grp = idx & 7;
                cp_async16(sA + (row * PAD_ + grp * 4) * 4,
                           A  + (size_t)(m0 + row) * K + k0 + grp * 4);
                cp_async16(sB + (row * PAD_ + grp * 4) * 4,
                           Bm + (size_t)(n0 + row) * K + k0 + grp * 4);
            }
            cp_commit();
            cp_wait1();
        } else {
            cp_wait0();
        }
        __syncthreads();

        const float* As = smem + (c & 1) * STAGE_FLOATS;
        const float* Bs = As + TILE_FLOATS;
        const uint32_t* Au = (const uint32_t*)As;
        const uint32_t* Bu = (const uint32_t*)Bs;

        #pragma unroll
        for (int kk = 0; kk < 32; kk += 8) {
            uint32_t ah[4][4], al[4][4], bh[4][2], bl[4][2];
            #pragma unroll
            for (int mi = 0; mi < 4; mi++) {
                const uint32_t* base = Au + (wm + mi * 16 + g) * PAD_ + kk + c4;
                split_tf32(base[0],            ah[mi][0], al[mi][0]);
                split_tf32(base[8 * PAD_],     ah[mi][1], al[mi][1]);
                split_tf32(base[4],            ah[mi][2], al[mi][2]);
                split_tf32(base[8 * PAD_ + 4], ah[mi][3], al[mi][3]);
            }
            #pragma unroll
            for (int ni = 0; ni < 4; ni++) {
                const uint32_t* base = Bu + (wn + ni * 8 + g) * PAD_ + kk + c4;
                split_tf32(base[0], bh[ni][0], bl[ni][0]);
                split_tf32(base[4], bh[ni][1], bl[ni][1]);
            }
            #pragma unroll
            for (int mi = 0; mi < 4; mi++)
                #pragma unroll
                for (int ni = 0; ni < 4; ni++) {
                    mma_tf32(acc[mi][ni][0], acc[mi][ni][1],
                             acc[mi][ni][2], acc[mi][ni][3],
                             ah[mi][0], ah[mi][1], ah[mi][2], ah[mi][3],
                             bl[ni][0], bl[ni][1]);
                    mma_tf32(acc[mi][ni][0], acc[mi][ni][1],
                             acc[mi][ni][2], acc[mi][ni][3],
                             al[mi][0], al[mi][1], al[mi][2], al[mi][3],
                             bh[ni][0], bh[ni][1]);
                    mma_tf32(acc[mi][ni][0], acc[mi][ni][1],
                             acc[mi][ni][2], acc[mi][ni][3],
                             ah[mi][0], ah[mi][1], ah[mi][2], ah[mi][3],
                             bh[ni][0], bh[ni][1]);
                }
        }
        __syncthreads();
    }

    #pragma unroll
    for (int mi = 0; mi < 4; mi++) {
        #pragma unroll
        for (int half = 0; half < 2; half++) {
            const int m = m0 + wm + mi * 16 + g + half * 8;
            if (mode == 0) {
                #pragma unroll
                for (int ni = 0; ni < 4; ni++) {
                    int n = n0 + wn + ni * 8 + c4 * 2;
                    float2 v = half == 0
                        ? make_float2(acc[mi][ni][0], acc[mi][ni][1])
                        : make_float2(acc[mi][ni][2], acc[mi][ni][3]);
                    *(float2*)(C + (size_t)m * N + n) = v;
                }
            } else {
                const int b = m >> 11;
                const int l = m & 2047;
                #pragma unroll
                for (int ni = 0; ni < 4; ni++) {
                    int n     = n0 + wn + ni * 8 + c4 * 2;
                    int which = n >> 10;
                    int rem   = n & 1023;
                    int h     = rem >> 6;
                    int d     = rem & 63;
                    size_t idx = (((size_t)(which * BH_ + b * H_ + h)) * L_ + l) * HD_ + d;
                    float2 v = half == 0
                        ? make_float2(acc[mi][ni][0], acc[mi][ni][1])
                        : make_float2(acc[mi][ni][2], acc[mi][ni][3]);
                    *(float2*)(C + idx) = v;
                }
            }
        }
    }
}

// ---------------------------------------------------------------------------
// Tensor-core flash attention, causal, 3xTF32 mma.sync.
// CTA = (64-query tile, head-stream). 128 threads = 4 warps; warp w owns
// q-rows w*16..w*16+15. Online softmax in registers (row pairs g, g+8 live
// in the m16n8 C-fragment); P re-fragmented via smem for the PV MMA.
// ---------------------------------------------------------------------------
#define APAD 68
#define ATT_SMEM_BYTES (4 * 64 * APAD * 4)   // Qs,Ks,Vts,Ss = 69632 B

__global__ __launch_bounds__(128) void attn_tc_kernel(
    const float* __restrict__ qkv, float* __restrict__ ctx)
{
    const int qt = blockIdx.x;    // query tile 0..31
    const int bh = blockIdx.y;    // 0..63

    extern __shared__ float sm[];
    float* Qs  = sm;                    // [q][d]   pad 68
    float* Ks  = sm + 64 * APAD;        // [k][d]   pad 68
    float* Vts = sm + 2 * 64 * APAD;    // [d][k]   pad 68 (V transposed)
    float* Ss  = sm + 3 * 64 * APAD;    // [q][k]   pad 68 (P tile)

    const int t    = threadIdx.x;
    const int w    = t >> 5;
    const int lane = t & 31;
    const int g    = lane >> 2;
    const int c4   = lane & 3;
    const int q0   = w * 16;            // warp's q-row base within tile

    const float* Qg = qkv + ((size_t)bh           * L_ + (size_t)qt * 64) * HD_;
    const float* Kg = qkv + ((size_t)(BH_ + bh)   * L_) * HD_;
    const float* Vg = qkv + ((size_t)(2*BH_ + bh) * L_) * HD_;

    // Load Q tile [64][64] row-major into Qs
    #pragma unroll
    for (int u = 0; u < 8; u++) {
        int idx = t + u * 128;          // 0..1023
        int row = idx >> 4;
        int cg  = idx & 15;
        float4 v = *(const float4*)(Qg + (size_t)row * HD_ + cg * 4);
        *(float4*)&Qs[row * APAD + cg * 4] = v;
    }

    float m0r = -1.0e30f, m1r = -1.0e30f;
    float l0r = 0.0f,     l1r = 0.0f;
    float oacc[8][4] = {};

    for (int kt = 0; kt <= qt; kt++) {
        __syncthreads();   // all warps done with Ks/Vts (and Q visible, iter 0)

        // Load K tile direct, V tile transposed
        #pragma unroll
        for (int u = 0; u < 8; u++) {
            int idx = t + u * 128;
            int row = idx >> 4;
            int cg  = idx & 15;
            float4 kv = *(const float4*)(Kg + ((size_t)(kt * 64 + row)) * HD_ + cg * 4);
            *(float4*)&Ks[row * APAD + cg * 4] = kv;
            float4 vv = *(const float4*)(Vg + ((size_t)(kt * 64 + row)) * HD_ + cg * 4);
            Vts[(cg * 4 + 0) * APAD + row] = vv.x;
            Vts[(cg * 4 + 1) * APAD + row] = vv.y;
            Vts[(cg * 4 + 2) * APAD + row] = vv.z;
            Vts[(cg * 4 + 3) * APAD + row] = vv.w;
        }
        __syncthreads();

        // ---- S = Q K^T (3xTF32), warp rows q0..q0+15, all 64 k-cols ----
        float sacc[8][4] = {};
        const uint32_t* Qu = (const uint32_t*)Qs;
        const uint32_t* Ku = (const uint32_t*)Ks;
        #pragma unroll
        for (int kk = 0; kk < 64; kk += 8) {
            uint32_t ah[4], al[4];
            {
                const uint32_t* base = Qu + (q0 + g) * APAD + kk + c4;
                split_tf32(base[0],            ah[0], al[0]);
                split_tf32(base[8 * APAD],     ah[1], al[1]);
                split_tf32(base[4],            ah[2], al[2]);
                split_tf32(base[8 * APAD + 4], ah[3], al[3]);
            }
            #pragma unroll
            for (int ni = 0; ni < 8; ni++) {
                uint32_t bh0, bl0, bh1, bl1;
                const uint32_t* base = Ku + (ni * 8 + g) * APAD + kk + c4;
                split_tf32(base[0], bh0, bl0);
                split_tf32(base[4], bh1, bl1);
                mma_tf32(sacc[ni][0], sacc[ni][1], sacc[ni][2], sacc[ni][3],
                         ah[0], ah[1], ah[2], ah[3], bl0, bl1);
                mma_tf32(sacc[ni][0], sacc[ni][1], sacc[ni][2], sacc[ni][3],
                         al[0], al[1], al[2], al[3], bh0, bh1);
                mma_tf32(sacc[ni][0], sacc[ni][1], sacc[ni][2], sacc[ni][3],
                         ah[0], ah[1], ah[2], ah[3], bh0, bh1);
            }
        }

        // ---- scale + causal mask ----
        const int qrow0 = qt * 64 + q0 + g;
        const int qrow1 = qrow0 + 8;
        #pragma unroll
        for (int ni = 0; ni < 8; ni++) {
            int col0 = kt * 64 + ni * 8 + c4 * 2;
            int col1 = col0 + 1;
            sacc[ni][0] = (col0 <= qrow0) ? sacc[ni][0] * 0.125f : -1.0e30f;
            sacc[ni][1] = (col1 <= qrow0) ? sacc[ni][1] * 0.125f : -1.0e30f;
            sacc[ni][2] = (col0 <= qrow1) ? sacc[ni][2] * 0.125f : -1.0e30f;
            sacc[ni][3] = (col1 <= qrow1) ? sacc[ni][3] * 0.125f : -1.0e30f;
        }

        // ---- online softmax (rows qrow0, qrow1) ----
        float mx0 = -1.0e30f, mx1 = -1.0e30f;
        #pragma unroll
        for (int ni = 0; ni < 8; ni++) {
            mx0 = fmaxf(mx0, fmaxf(sacc[ni][0], sacc[ni][1]));
            mx1 = fmaxf(mx1, fmaxf(sacc[ni][2], sacc[ni][3]));
        }
        mx0 = fmaxf(mx0, __shfl_xor_sync(0xffffffffu, mx0, 1));
        mx0 = fmaxf(mx0, __shfl_xor_sync(0xffffffffu, mx0, 2));
        mx1 = fmaxf(mx1, __shfl_xor_sync(0xffffffffu, mx1, 1));
        mx1 = fmaxf(mx1, __shfl_xor_sync(0xffffffffu, mx1, 2));

        float mn0 = fmaxf(m0r, mx0);
        float mn1 = fmaxf(m1r, mx1);
        float corr0 = __expf(m0r - mn0);
        float corr1 = __expf(m1r - mn1);
        m0r = mn0; m1r = mn1;

        float sum0 = 0.0f, sum1 = 0.0f;
        #pragma unroll
        for (int ni = 0; ni < 8; ni++) {
            sacc[ni][0] = __expf(sacc[ni][0] - mn0); sum0 += sacc[ni][0];
            sacc[ni][1] = __expf(sacc[ni][1] - mn0); sum0 += sacc[ni][1];
            sacc[ni][2] = __expf(sacc[ni][2] - mn1); sum1 += sacc[ni][2];
            sacc[ni][3] = __expf(sacc[ni][3] - mn1); sum1 += sacc[ni][3];
        }
        sum0 += __shfl_xor_sync(0xffffffffu, sum0, 1);
        sum0 += __shfl_xor_sync(0xffffffffu, sum0, 2);
        sum1 += __shfl_xor_sync(0xffffffffu, sum1, 1);
        sum1 += __shfl_xor_sync(0xffffffffu, sum1, 2);
        l0r = l0r * corr0 + sum0;
        l1r = l1r * corr1 + sum1;

        // rescale O accumulator
        #pragma unroll
        for (int ni = 0; ni < 8; ni++) {
            oacc[ni][0] *= corr0; oacc[ni][1] *= corr0;
            oacc[ni][2] *= corr1; oacc[ni][3] *= corr1;
        }

        // ---- stage P into Ss (own warp's 16 rows only) ----
        #pragma unroll
        for (int ni = 0; ni < 8; ni++) {
            *(float2*)&Ss[(q0 + g    ) * APAD + ni * 8 + c4 * 2] =
                make_float2(sacc[ni][0], sacc[ni][1]);
            *(float2*)&Ss[(q0 + g + 8) * APAD + ni * 8 + c4 * 2] =
                make_float2(sacc[ni][2], sacc[ni][3]);
        }
        __syncwarp();

        // ---- O += P V   (A = P from Ss, B = V^T from Vts), 3xTF32 ----
        const uint32_t* Pu = (const uint32_t*)Ss;
        const uint32_t* Vu = (const uint32_t*)Vts;
        #pragma unroll
        for (int kk = 0; kk < 64; kk += 8) {
            uint32_t ah[4], al[4];
            {
                const uint32_t* base = Pu + (q0 + g) * APAD + kk + c4;
                split_tf32(base[0],            ah[0], al[0]);
                split_tf32(base[8 * APAD],     ah[1], al[1]);
                split_tf32(base[4],            ah[2], al[2]);
                split_tf32(base[8 * APAD + 4], ah[3], al[3]);
            }
            #pragma unroll
            for (int ni = 0; ni < 8; ni++) {
                uint32_t bh0, bl0, bh1, bl1;
                const uint32_t* base = Vu + (ni * 8 + g) * APAD + kk + c4;
                split_tf32(base[0], bh0, bl0);
                split_tf32(base[4], bh1, bl1);
                mma_tf32(oacc[ni][0], oacc[ni][1], oacc[ni][2], oacc[ni][3],
                         ah[0], ah[1], ah[2], ah[3], bl0, bl1);
                mma_tf32(oacc[ni][0], oacc[ni][1], oacc[ni][2], oacc[ni][3],
                         al[0], al[1], al[2], al[3], bh0, bh1);
                mma_tf32(oacc[ni][0], oacc[ni][1], oacc[ni][2], oacc[ni][3],
                         ah[0], ah[1], ah[2], ah[3], bh0, bh1);
            }
        }
    }

    // ---- normalize + write ctx [B][L][H][HD] ----
    const int b = bh >> 4;
    const int h = bh & 15;
    const float inv0 = 1.0f / l0r;
    const float inv1 = 1.0f / l1r;
    const int l0i = qt * 64 + q0 + g;
    const int l1i = l0i + 8;
    #pragma unroll
    for (int ni = 0; ni < 8; ni++) {
        int d = ni * 8 + c4 * 2;
        size_t i0 = (((size_t)b * L_ + l0i) * H_ + h) * HD_ + d;
        size_t i1 = (((size_t)b * L_ + l1i) * H_ + h) * HD_ + d;
        *(float2*)(ctx + i0) = make_float2(oacc[ni][0] * inv0, oacc[ni][1] * inv0);
        *(float2*)(ctx + i1) = make_float2(oacc[ni][2] * inv1, oacc[ni][3] * inv1);
    }
}

// ---------------------------------------------------------------------------
extern "C" void kernel_launch(void* const* d_in, const int* in_sizes, int n_in,
                              void* d_out, int out_size)
{
    const float* x     = (const float*)d_in[0];   // [B,L,D]
    const float* W_qkv = (const float*)d_in[1];   // [3D, D]
    const float* W_out = (const float*)d_in[2];   // [D, D]
    float* out = (float*)d_out;                   // [B,L,D]

    float* qkv_ptr = nullptr;
    float* ctx_ptr = nullptr;
    cudaGetSymbolAddress((void**)&qkv_ptr, g_qkv);
    cudaGetSymbolAddress((void**)&ctx_ptr, g_ctx);

    cudaFuncSetAttribute(gemm_tc_kernel,
                         cudaFuncAttributeMaxDynamicSharedMemorySize, GK_SMEM_BYTES);
    cudaFuncSetAttribute(attn_tc_kernel,
                         cudaFuncAttributeMaxDynamicSharedMemorySize, ATT_SMEM_BYTES);

    // 1) QKV projection (3xTF32 mma.sync) with scatter epilogue
    gemm_tc_kernel<<<dim3(3 * D_ / 128, NT_ / 128), 256, GK_SMEM_BYTES>>>(
        x, W_qkv, qkv_ptr, NT_, 3 * D_, D_, 1);

    // 2) causal flash attention (3xTF32 mma.sync)
    attn_tc_kernel<<<dim3(L_ / 64, BH_), 128, ATT_SMEM_BYTES>>>(qkv_ptr, ctx_ptr);

    // 3) output projection (3xTF32 mma.sync)
    gemm_tc_kernel<<<dim3(D_ / 128, NT_ / 128), 256, GK_SMEM_BYTES>>>(
        ctx_ptr, W_out, out, NT_, D_, D_, 0);
}